// round 11
// baseline (speedup 1.0000x reference)
#include <cuda_runtime.h>

#define TSTEPS  1024
#define BATCH   64
#define IN_DIM  256
#define HID_DIM 512
#define OUT_DIM 256
#define KDIM    768
#define NCTA    128
#define NTHR    768

// strides in floats
#define HSTRIDE_B (1025 * HID_DIM)
#define RSTRIDE_B (1025 * OUT_DIM)
#define XSTRIDE_B (TSTEPS * IN_DIM)

// ---- global-barrier state (init + final reset only) ----
__device__ unsigned g_bar_count = 0;
__device__ volatile unsigned g_bar_gen = 0;

// ---- monotonic epoch counters: [0]=h half0, [64]=h half1, [128]=r h0, [192]=r h1 ----
__device__ unsigned g_cnt[4 * 64];

__device__ __forceinline__ void grid_barrier() {
    __syncthreads();
    if (threadIdx.x == 0) {
        __threadfence();
        unsigned g = g_bar_gen;
        if (atomicAdd(&g_bar_count, 1u) == NCTA - 1) {
            g_bar_count = 0;
            __threadfence();
            g_bar_gen = g + 1;
        } else {
            while (g_bar_gen == g) {}
            __threadfence();
        }
    }
    __syncthreads();
}

__device__ __forceinline__ void red_release_add1(unsigned* p) {
    asm volatile("red.release.gpu.add.u32 [%0], 1;" :: "l"(p) : "memory");
}
__device__ __forceinline__ unsigned ld_acquire_u32(const unsigned* p) {
    unsigned v;
    asm volatile("ld.acquire.gpu.u32 %0, [%1];" : "=r"(v) : "l"(p) : "memory");
    return v;
}
__device__ __forceinline__ void bar_sync(int id, int nthr) {
    asm volatile("bar.sync %0, %1;" :: "r"(id), "r"(nthr) : "memory");
}

// Persistent RNN kernel, v8: DECOUPLED h-chain / r-chain warp specialization.
// 128 CTAs = 64 column-groups x 2 batch-halves. CTA = 768 threads = 24 warps.
//   h-chain (warps 0..15): 8 h-cols x 32 batch. warp = (col-half ch) x (batch-oct).
//     per-iter: x-dot (prefolded) + h-dot, 384 FFMA/thr. Sync: hcnt epochs, bar 1.
//   r-chain (warps 16..23): 4 r-cols x 32 batch. warp = batch-oct.
//     per-iter: h-part + r-part dots, 384 FFMA/thr. Sync: hcnt(it) + rcnt(it-1), bar 2.
// h never waits on r -> runtime = max(chains), r-warps fill h-stall issue slots.
__global__ void __launch_bounds__(NTHR, 1)
rnn_persistent_kernel(const float* __restrict__ X,    // [64][1024][256]
                      const float* __restrict__ H0,   // [64][512]
                      const float* __restrict__ R0,   // [64][256]
                      const float* __restrict__ Wih,  // [512][768]
                      const float* __restrict__ Bih,  // [512]
                      const float* __restrict__ Who,  // [256][768]
                      const float* __restrict__ Bho,  // [256]
                      float* __restrict__ Rout,       // [64][1025][256]
                      float* __restrict__ Hout)       // [64][1025][512]
{
    __shared__ float W1s[8][KDIM];   // W_ih rows jh0.. (k: 0..255 x | 256..767 h)
    __shared__ float W2s[4][KDIM];   // W_ho rows jr0.. (k: 0..511 h | 512..767 r)
    __shared__ float bih_s[8];
    __shared__ float bho_s[4];
    volatile __shared__ int h_flag;
    volatile __shared__ int r_flag;

    const int tid  = threadIdx.x;
    const int cta  = blockIdx.x;
    const int grp  = cta >> 1;
    const int half = cta & 1;
    const int b0   = half * 32;
    const int jh0  = grp * 8;
    const int jr0  = grp * 4;
    const int wrp  = tid >> 5;
    const int lane = tid & 31;
    unsigned* hcnt = &g_cnt[half * 64];
    unsigned* rcnt = &g_cnt[128 + half * 64];

    // ---- stationary weight slices -> smem ----
    for (int idx = tid; idx < 8 * KDIM; idx += NTHR) {
        int j = idx / KDIM, k = idx - j * KDIM;
        W1s[j][k] = Wih[(jh0 + j) * KDIM + k];
    }
    for (int idx = tid; idx < 4 * KDIM; idx += NTHR) {
        int j = idx / KDIM, k = idx - j * KDIM;
        W2s[j][k] = Who[(jr0 + j) * KDIM + k];
    }
    if (tid < 8) bih_s[tid] = Bih[jh0 + tid];
    if (tid < 4) bho_s[tid] = Bho[jr0 + tid];
    if (tid == 0) { h_flag = 0; r_flag = 0; }

    // ---- t=0 states into output/exchange buffers ----
    for (int idx = tid; idx < 32 * 8; idx += NTHR) {
        int b = b0 + (idx >> 3), jj = idx & 7;
        Hout[(size_t)b * HSTRIDE_B + jh0 + jj] = H0[b * HID_DIM + jh0 + jj];
    }
    for (int idx = tid; idx < 32 * 4; idx += NTHR) {
        int b = b0 + (idx >> 2), jj = idx & 3;
        Rout[(size_t)b * RSTRIDE_B + jr0 + jj] = R0[b * OUT_DIM + jr0 + jj];
    }
    __syncthreads();   // weights/biases/flags/states ready CTA-wide

    float A[16];
#pragma unroll
    for (int i = 0; i < 16; ++i) A[i] = 0.f;

    // ======================= h-chain setup + prologue =======================
    const int ch   = wrp >> 3;        // (h-warps) col half
    const int boct = wrp & 7;         // (h-warps) batch oct
    const int hb0  = b0 + boct * 4;

    if (wrp < 16) {
        const float* pX0 = X + (size_t)hb0 * XSTRIDE_B + 4 * lane;
        // prologue: fold x[0]
#pragma unroll
        for (int i = 0; i < 2; ++i) {
            float4 w[4];
#pragma unroll
            for (int c = 0; c < 4; ++c)
                w[c] = *(const float4*)&W1s[ch * 4 + c][4 * lane + 128 * i];
#pragma unroll
            for (int b = 0; b < 4; ++b) {
                const float4 a = *(const float4*)&pX0[b * XSTRIDE_B + 128 * i];
#pragma unroll
                for (int c = 0; c < 4; ++c)
                    A[b * 4 + c] += a.x * w[c].x + a.y * w[c].y
                                  + a.z * w[c].z + a.w * w[c].w;
            }
        }
    }

    grid_barrier();   // all CTAs' t=0 states visible chip-wide

    if (wrp < 16) {
        // ============================ h-chain ============================
        const float* pHr = Hout + (size_t)hb0 * HSTRIDE_B + 4 * lane;   // h[t=0]
        const float* pX  = X    + (size_t)hb0 * XSTRIDE_B + 4 * lane + IN_DIM; // x[t=1]
        float* pW = 0; float bias = 0.f;
        if (lane < 16) {
            const int bl = lane >> 2, c = lane & 3;
            pW   = Hout + (size_t)(hb0 + bl) * HSTRIDE_B + HID_DIM + jh0 + ch * 4 + c;
            bias = bih_s[ch * 4 + c];
        }

        for (int it = 0; it < TSTEPS; ++it) {
            // wait: h[it] visible (hcnt >= 64*it); tid0 polls, others spin on smem flag
            if (tid == 0) {
                const unsigned tgt = 64u * (unsigned)it;
                while ((int)(ld_acquire_u32(hcnt) - tgt) < 0) {}
                h_flag = it;
            } else if (lane == 0) {
                while (h_flag < it) {}
            }
            __syncwarp();

            // h-dot (A already holds x[it] part)
#pragma unroll
            for (int i = 0; i < 4; ++i) {
                float4 w[4];
#pragma unroll
                for (int c = 0; c < 4; ++c)
                    w[c] = *(const float4*)&W1s[ch * 4 + c][256 + 4 * lane + 128 * i];
#pragma unroll
                for (int b = 0; b < 4; ++b) {
                    const float4 a = *(const float4*)&pHr[b * HSTRIDE_B + 128 * i];
#pragma unroll
                    for (int c = 0; c < 4; ++c)
                        A[b * 4 + c] += a.x * w[c].x + a.y * w[c].y
                                      + a.z * w[c].z + a.w * w[c].w;
                }
            }

            // transpose-butterfly reduce (15 shuffles), lane L (<16) gets output L
#pragma unroll
            for (int off = 16; off >= 1; off >>= 1) {
#pragma unroll
                for (int i = 0; i < off && i < 16; ++i) {
                    const int j = i + off;
                    const float vj = (j < 16) ? A[j] : 0.f;
                    const float send = (lane & off) ? A[i] : vj;
                    const float recv = __shfl_xor_sync(0xffffffffu, send, off);
                    const float keep = (lane & off) ? vj : A[i];
                    A[i] = keep + recv;
                }
            }

            if (lane < 16) *pW = fmaxf(A[0] + bias, 0.f);   // h[it+1]

            bar_sync(1, 512);                     // all h-warp stores issued
            if (tid == 0) red_release_add1(hcnt); // h-epoch -> it+1

            // wait-window: zero accs, prefold x[it+1], advance pointers
#pragma unroll
            for (int i = 0; i < 16; ++i) A[i] = 0.f;
            if (it + 1 < TSTEPS) {
#pragma unroll
                for (int i = 0; i < 2; ++i) {
                    float4 w[4];
#pragma unroll
                    for (int c = 0; c < 4; ++c)
                        w[c] = *(const float4*)&W1s[ch * 4 + c][4 * lane + 128 * i];
#pragma unroll
                    for (int b = 0; b < 4; ++b) {
                        const float4 a = *(const float4*)&pX[b * XSTRIDE_B + 128 * i];
#pragma unroll
                        for (int c = 0; c < 4; ++c)
                            A[b * 4 + c] += a.x * w[c].x + a.y * w[c].y
                                          + a.z * w[c].z + a.w * w[c].w;
                    }
                }
            }
            pX  += IN_DIM;
            pHr += HID_DIM;
            if (lane < 16) pW += HID_DIM;
        }
    } else {
        // ============================ r-chain ============================
        const int rw  = wrp - 16;          // batch oct
        const int rb0 = b0 + rw * 4;
        const float* pHr = Hout + (size_t)rb0 * HSTRIDE_B + HID_DIM + 4 * lane; // h[t=1]
        const float* pRr = Rout + (size_t)rb0 * RSTRIDE_B + 4 * lane;           // r[t=0]
        float* pW = 0; float bias = 0.f;
        if (lane < 16) {
            const int bl = lane >> 2, c = lane & 3;
            pW   = Rout + (size_t)(rb0 + bl) * RSTRIDE_B + OUT_DIM + jr0 + c;   // r[t=1]
            bias = bho_s[c];
        }

        for (int it = 1; it <= TSTEPS; ++it) {
            // wait: h[it] visible AND r[it-1] visible; tid 512 polls, relays via r_flag
            if (tid == 512) {
                const unsigned tgtH = 64u * (unsigned)it;
                while ((int)(ld_acquire_u32(hcnt) - tgtH) < 0) {}
                const unsigned tgtR = 64u * (unsigned)(it - 1);
                while ((int)(ld_acquire_u32(rcnt) - tgtR) < 0) {}
                r_flag = it;
            } else if (lane == 0) {
                while (r_flag < it) {}
            }
            __syncwarp();

            // h-part dot (W_ho k=0..511)
#pragma unroll
            for (int i = 0; i < 4; ++i) {
                float4 w[4];
#pragma unroll
                for (int c = 0; c < 4; ++c)
                    w[c] = *(const float4*)&W2s[c][4 * lane + 128 * i];
#pragma unroll
                for (int b = 0; b < 4; ++b) {
                    const float4 a = *(const float4*)&pHr[b * HSTRIDE_B + 128 * i];
#pragma unroll
                    for (int c = 0; c < 4; ++c)
                        A[b * 4 + c] += a.x * w[c].x + a.y * w[c].y
                                      + a.z * w[c].z + a.w * w[c].w;
                }
            }
            // r-part dot (W_ho k=512..767)
#pragma unroll
            for (int i = 0; i < 2; ++i) {
                float4 w[4];
#pragma unroll
                for (int c = 0; c < 4; ++c)
                    w[c] = *(const float4*)&W2s[c][512 + 4 * lane + 128 * i];
#pragma unroll
                for (int b = 0; b < 4; ++b) {
                    const float4 a = *(const float4*)&pRr[b * RSTRIDE_B + 128 * i];
#pragma unroll
                    for (int c = 0; c < 4; ++c)
                        A[b * 4 + c] += a.x * w[c].x + a.y * w[c].y
                                      + a.z * w[c].z + a.w * w[c].w;
                }
            }

            // reduce
#pragma unroll
            for (int off = 16; off >= 1; off >>= 1) {
#pragma unroll
                for (int i = 0; i < off && i < 16; ++i) {
                    const int j = i + off;
                    const float vj = (j < 16) ? A[j] : 0.f;
                    const float send = (lane & off) ? A[i] : vj;
                    const float recv = __shfl_xor_sync(0xffffffffu, send, off);
                    const float keep = (lane & off) ? vj : A[i];
                    A[i] = keep + recv;
                }
            }

            if (lane < 16) *pW = fmaxf(A[0] + bias, 0.f);   // r[it]

            if (it == TSTEPS) break;

            bar_sync(2, 256);                       // all r-warp stores issued
            if (tid == 512) red_release_add1(rcnt); // r-epoch -> it

#pragma unroll
            for (int i = 0; i < 16; ++i) A[i] = 0.f;
            pHr += HID_DIM;
            pRr += OUT_DIM;
            if (lane < 16) pW += OUT_DIM;
        }
    }

    // ---- reset epoch counters for the next graph replay ----
    grid_barrier();
    if (cta < 4 && tid == 0) g_cnt[cta * 64] = 0;
}

extern "C" void kernel_launch(void* const* d_in, const int* in_sizes, int n_in,
                              void* d_out, int out_size) {
    const float* X   = (const float*)d_in[0];
    const float* H0  = (const float*)d_in[1];
    const float* R0  = (const float*)d_in[2];
    const float* Wih = (const float*)d_in[3];
    const float* Bih = (const float*)d_in[4];
    const float* Who = (const float*)d_in[5];
    const float* Bho = (const float*)d_in[6];

    float* Rout = (float*)d_out;                                   // [64][1025][256]
    float* Hout = (float*)d_out + (size_t)BATCH * 1025 * OUT_DIM;  // [64][1025][512]

    rnn_persistent_kernel<<<NCTA, NTHR>>>(X, H0, R0, Wih, Bih, Who, Bho, Rout, Hout);
}

// round 12
// speedup vs baseline: 2.4050x; 2.4050x over previous
#include <cuda_runtime.h>

#define TSTEPS  1024
#define BATCH   64
#define IN_DIM  256
#define HID_DIM 512
#define OUT_DIM 256
#define KDIM    768
#define NCTA    128
#define NTHR    512

// strides in floats
#define HSTRIDE_B (1025 * HID_DIM)
#define RSTRIDE_B (1025 * OUT_DIM)
#define XSTRIDE_B (TSTEPS * IN_DIM)

// smem: W1s[32][768] + W2s[16][768] + biases
#define W1_ROWS 32
#define W2_ROWS 16
#define SMEM_FLOATS (W1_ROWS * KDIM + W2_ROWS * KDIM + W1_ROWS + W2_ROWS)

// ---- global-barrier state (init + final reset only) ----
__device__ unsigned g_bar_count = 0;
__device__ volatile unsigned g_bar_gen = 0;

// ---- per-batch-group monotonic epoch counters (separate 256B L2 sectors) ----
__device__ unsigned g_cnt[8 * 64];

__device__ __forceinline__ void grid_barrier() {
    __syncthreads();
    if (threadIdx.x == 0) {
        __threadfence();
        unsigned g = g_bar_gen;
        if (atomicAdd(&g_bar_count, 1u) == NCTA - 1) {
            g_bar_count = 0;
            __threadfence();
            g_bar_gen = g + 1;
        } else {
            while (g_bar_gen == g) {}
            __threadfence();
        }
    }
    __syncthreads();
}

__device__ __forceinline__ void red_release_add1(unsigned* p) {
    asm volatile("red.release.gpu.add.u32 [%0], 1;" :: "l"(p) : "memory");
}
__device__ __forceinline__ unsigned ld_acquire_u32(const unsigned* p) {
    unsigned v;
    asm volatile("ld.acquire.gpu.u32 %0, [%1];" : "=r"(v) : "l"(p) : "memory");
    return v;
}

// Persistent RNN kernel, v9 = v5 loop body on a 16-CTA sync domain.
// 128 CTAs = 8 batch-groups x 16 col-groups. CTA = 512 threads = 16 warps.
//   col-group cg owns h-cols [cg*32,cg*32+32), r-cols [cg*16,cg*16+16)
//   batch-group bg owns rows [bg*8, bg*8+8)
//   warp = (col-part cp in 0..7) x (row-half rh): 4 h-cols + 2 r-cols x 4 rows
//   lane = k-slice (k = 4*lane + 128*i), float4, plain FFMA; 576 FFMA/thr/iter.
// Sync: per-bg epoch counter, 16 arrivals/iter (red.release + single-poller
// acquire, smem flag relay). x-dot for it+1 folded in the wait window.
// The 8 col-part warps share the same 8 h-rows -> 7/8 of h loads are L1 hits.
__global__ void __launch_bounds__(NTHR, 1)
rnn_persistent_kernel(const float* __restrict__ X,    // [64][1024][256]
                      const float* __restrict__ H0,   // [64][512]
                      const float* __restrict__ R0,   // [64][256]
                      const float* __restrict__ Wih,  // [512][768]
                      const float* __restrict__ Bih,  // [512]
                      const float* __restrict__ Who,  // [256][768]
                      const float* __restrict__ Bho,  // [256]
                      float* __restrict__ Rout,       // [64][1025][256]
                      float* __restrict__ Hout)       // [64][1025][512]
{
    extern __shared__ float smem[];
    float* W1s   = smem;                     // [32][768]
    float* W2s   = smem + W1_ROWS * KDIM;    // [16][768]
    float* bih_s = W2s + W2_ROWS * KDIM;     // [32]
    float* bho_s = bih_s + W1_ROWS;          // [16]
    volatile __shared__ int bar_flag;

    const int tid  = threadIdx.x;
    const int cta  = blockIdx.x;
    const int bg   = cta & 7;         // batch group (8 rows)
    const int cg   = cta >> 3;        // col group (32 h + 16 r cols)
    const int b0   = bg * 8;
    const int jh0  = cg * 32;
    const int jr0  = cg * 16;
    const int wrp  = tid >> 5;
    const int lane = tid & 31;
    const int cp   = wrp >> 1;        // col part: 4 h-cols + 2 r-cols
    const int rh   = wrp & 1;         // row half
    const int bb0  = b0 + rh * 4;
    unsigned* cnt  = &g_cnt[bg * 64];

    // ---- stationary weight slices -> smem (coalesced over k) ----
    for (int idx = tid; idx < W1_ROWS * KDIM; idx += NTHR) {
        int j = idx / KDIM, k = idx - j * KDIM;
        W1s[idx] = Wih[(jh0 + j) * KDIM + k];
    }
    for (int idx = tid; idx < W2_ROWS * KDIM; idx += NTHR) {
        int j = idx / KDIM, k = idx - j * KDIM;
        W2s[idx] = Who[(jr0 + j) * KDIM + k];
    }
    if (tid < W1_ROWS) bih_s[tid] = Bih[jh0 + tid];
    if (tid < W2_ROWS) bho_s[tid] = Bho[jr0 + tid];
    if (tid == 0) bar_flag = 0;

    // ---- t=0 states into output/exchange buffers ----
    for (int idx = tid; idx < 8 * 32; idx += NTHR) {
        int b = b0 + (idx >> 5), jj = idx & 31;
        Hout[(size_t)b * HSTRIDE_B + jh0 + jj] = H0[b * HID_DIM + jh0 + jj];
    }
    for (int idx = tid; idx < 8 * 16; idx += NTHR) {
        int b = b0 + (idx >> 4), jj = idx & 15;
        Rout[(size_t)b * RSTRIDE_B + jr0 + jj] = R0[b * OUT_DIM + jr0 + jj];
    }
    __syncthreads();   // weights + flag + states ready

    // ---- per-warp smem weight bases ----
    const float* W1p = &W1s[(cp * 4) * KDIM];   // 4 h-col rows
    const float* W2p = &W2s[(cp * 2) * KDIM];   // 2 r-col rows

    // ---- running pointers ----
    const float* pHr = Hout + (size_t)bb0 * HSTRIDE_B + 4 * lane;           // h[t=0]
    const float* pX  = X    + (size_t)bb0 * XSTRIDE_B + 4 * lane;           // x[t=0]
    const float* pRr = Rout + (size_t)bb0 * RSTRIDE_B + 4 * lane - OUT_DIM; // r[t=-1] (guarded)

    // per-lane store pointer + bias: lane<24, flat out idx = lane
    const int bl = lane / 6, oc = lane % 6;
    float* pW = 0; float bias = 0.f; int wstep = 0;
    if (lane < 24) {
        if (oc < 4) {   // h output: slot t=1, stores h[it+1]
            pW    = Hout + (size_t)(bb0 + bl) * HSTRIDE_B + HID_DIM + jh0 + cp * 4 + oc;
            bias  = bih_s[cp * 4 + oc];
            wstep = HID_DIM;
        } else {        // r output: slot t=0, stores r[it] (guarded it>=1)
            pW    = Rout + (size_t)(bb0 + bl) * RSTRIDE_B + jr0 + cp * 2 + (oc - 4);
            bias  = bho_s[cp * 2 + (oc - 4)];
            wstep = OUT_DIM;
        }
    }

    // A[b*6+c]: c 0..3 h-cols, c 4..5 r-cols
    float A[24];
#pragma unroll
    for (int i = 0; i < 24; ++i) A[i] = 0.f;

    // ---- prologue: x-dot for it=0 ----
#pragma unroll
    for (int i = 0; i < 2; ++i) {
        float4 w[4];
#pragma unroll
        for (int c = 0; c < 4; ++c) w[c] = *(const float4*)&W1p[c * KDIM + 4 * lane + 128 * i];
#pragma unroll
        for (int b = 0; b < 4; ++b) {
            const float4 a = *(const float4*)&pX[b * XSTRIDE_B + 128 * i];
#pragma unroll
            for (int c = 0; c < 4; ++c)
                A[b * 6 + c] += a.x * w[c].x + a.y * w[c].y
                              + a.z * w[c].z + a.w * w[c].w;
        }
    }
    pX += IN_DIM;

    grid_barrier();  // one-time: all t=0 states visible chip-wide

    for (int it = 0; it <= TSTEPS; ++it) {
        // ---- h[it] feeds h-dot (W_ih k=256..767) and r-dot (W_ho k=0..511) ----
#pragma unroll
        for (int i = 0; i < 4; ++i) {
            float4 w1[4], w2[2];
#pragma unroll
            for (int c = 0; c < 4; ++c) w1[c] = *(const float4*)&W1p[c * KDIM + 256 + 4 * lane + 128 * i];
#pragma unroll
            for (int c = 0; c < 2; ++c) w2[c] = *(const float4*)&W2p[c * KDIM + 4 * lane + 128 * i];
#pragma unroll
            for (int b = 0; b < 4; ++b) {
                const float4 a = *(const float4*)&pHr[b * HSTRIDE_B + 128 * i];
#pragma unroll
                for (int c = 0; c < 4; ++c)
                    A[b * 6 + c] += a.x * w1[c].x + a.y * w1[c].y
                                  + a.z * w1[c].z + a.w * w1[c].w;
#pragma unroll
                for (int c = 0; c < 2; ++c)
                    A[b * 6 + 4 + c] += a.x * w2[c].x + a.y * w2[c].y
                                      + a.z * w2[c].z + a.w * w2[c].w;
            }
        }

        // ---- r[it-1] contribution (W_ho k = 512..767) ----
        if (it >= 1) {
#pragma unroll
            for (int i = 0; i < 2; ++i) {
                float4 w2[2];
#pragma unroll
                for (int c = 0; c < 2; ++c) w2[c] = *(const float4*)&W2p[c * KDIM + 512 + 4 * lane + 128 * i];
#pragma unroll
                for (int b = 0; b < 4; ++b) {
                    const float4 a = *(const float4*)&pRr[b * RSTRIDE_B + 128 * i];
#pragma unroll
                    for (int c = 0; c < 2; ++c)
                        A[b * 6 + 4 + c] += a.x * w2[c].x + a.y * w2[c].y
                                          + a.z * w2[c].z + a.w * w2[c].w;
                }
            }
        }

        // ---- transpose-butterfly reduction: 31 shuffles, output L lands on lane L ----
#pragma unroll
        for (int off = 16; off >= 1; off >>= 1) {
#pragma unroll
            for (int i = 0; i < off && i < 24; ++i) {
                const int j = i + off;
                const float vj = (j < 24) ? A[j] : 0.f;
                const float send = (lane & off) ? A[i] : vj;
                const float recv = __shfl_xor_sync(0xffffffffu, send, off);
                const float keep = (lane & off) ? vj : A[i];
                A[i] = keep + recv;
            }
        }

        // ---- bias + relu + store ----
        if (lane < 24) {
            const float v = fmaxf(A[0] + bias, 0.f);
            if (oc < 4) {
                if (it < TSTEPS) *pW = v;   // h[it+1]
            } else {
                if (it >= 1) *pW = v;       // r[it]
            }
        }

        if (it == TSTEPS) break;

        __syncthreads();                       // all CTA stores issued
        if (tid == 0) red_release_add1(cnt);   // arrive (release)

        // ---- wait window: zero accs, fold x-dot for it+1, advance pointers ----
#pragma unroll
        for (int i = 0; i < 24; ++i) A[i] = 0.f;
        if (it + 1 < TSTEPS) {
#pragma unroll
            for (int i = 0; i < 2; ++i) {
                float4 w[4];
#pragma unroll
                for (int c = 0; c < 4; ++c) w[c] = *(const float4*)&W1p[c * KDIM + 4 * lane + 128 * i];
#pragma unroll
                for (int b = 0; b < 4; ++b) {
                    const float4 a = *(const float4*)&pX[b * XSTRIDE_B + 128 * i];
#pragma unroll
                    for (int c = 0; c < 4; ++c)
                        A[b * 6 + c] += a.x * w[c].x + a.y * w[c].y
                                      + a.z * w[c].z + a.w * w[c].w;
                }
            }
        }
        pX  += IN_DIM;
        pHr += HID_DIM;
        pRr += OUT_DIM;
        if (lane < 24) pW += wstep;

        // ---- wait for this batch-group's epoch (16 arrivals/iter) ----
        const int epoch = it + 1;
        if (tid == 0) {
            const unsigned tgt = 16u * (unsigned)epoch;
            while ((int)(ld_acquire_u32(cnt) - tgt) < 0) {}
            bar_flag = epoch;
        } else if (lane == 0) {
            while (bar_flag < epoch) {}
        }
        __syncwarp();
    }

    // ---- reset epoch counters for the next graph replay ----
    grid_barrier();
    if (cta < 8 && tid == 0) g_cnt[cta * 64] = 0;
}

extern "C" void kernel_launch(void* const* d_in, const int* in_sizes, int n_in,
                              void* d_out, int out_size) {
    const float* X   = (const float*)d_in[0];
    const float* H0  = (const float*)d_in[1];
    const float* R0  = (const float*)d_in[2];
    const float* Wih = (const float*)d_in[3];
    const float* Bih = (const float*)d_in[4];
    const float* Who = (const float*)d_in[5];
    const float* Bho = (const float*)d_in[6];

    float* Rout = (float*)d_out;                                   // [64][1025][256]
    float* Hout = (float*)d_out + (size_t)BATCH * 1025 * OUT_DIM;  // [64][1025][512]

    static int smem_set = 0;
    const int smem_bytes = SMEM_FLOATS * (int)sizeof(float);
    if (!smem_set) {
        cudaFuncSetAttribute(rnn_persistent_kernel,
                             cudaFuncAttributeMaxDynamicSharedMemorySize, smem_bytes);
        smem_set = 1;
    }
    rnn_persistent_kernel<<<NCTA, NTHR, smem_bytes>>>(X, H0, R0, Wih, Bih, Who, Bho,
                                                      Rout, Hout);
}